// round 12
// baseline (speedup 1.0000x reference)
#include <cuda_runtime.h>
#include <cstdint>

#define TT 64
#define CC 128
#define HD 32
#define NTHREADS 256

// k-interleave permutation within each 8-group: col c -> slot
//   slot(c) = ((c&3)<<1) | ((c>>2)&1)      (pairs (t, t+4) -> (2t, 2t+1))
//   inv(s)  = ((s>>1)&3) | ((s&1)<<2)
#define PSLOT8(l) ((((l) & 3) << 1) | (((l) >> 2) & 1))

// Strides for LDS.64 fragment loads: S ≡ 8 (mod 32) -> conflict-free per half-warp
#define XHS 40     // x quarter tf32 [64][40] k-permuted (A)      extent 32 ✓
#define QSS 40     // q tf32 [64][40] d-permuted (A)              extent 32 ✓
#define KSS 40     // k tf32 [64][40] d-permuted (B n-major)      extent 32 ✓
#define VTS 72     // vT tf32 [32][72] [d][seq-permuted] (B)      extent 64 ✓
#define SCS 72     // scores/probs [64][72] seq-col-permuted (A)  extent 64 ✓

#define OFF_XH 0
#define OFF_WH (TT * XHS)                    // 2560
#define STAGE_WORDS (OFF_WH + 12 * 256)      // 5632 (sc overlay 64*72=4608 fits)
#define OFF_Q  STAGE_WORDS                   // 5632
#define OFF_K  (OFF_Q + TT * QSS)            // 8192
#define OFF_VT (OFF_K + TT * KSS)            // 10752
#define SMEM_WORDS (OFF_VT + HD * VTS)       // 13056 words = 52224 B

// fragment-major tf32 W: [j=0..11][ks=0..15][lane=0..31][2]
__device__ uint32_t g_Wfrag[12 * 16 * 32 * 2];

__device__ __forceinline__ uint32_t f2tf(float f) {
    uint32_t u;
    asm("cvt.rna.tf32.f32 %0, %1;" : "=r"(u) : "f"(f));
    return u;
}
__device__ __forceinline__ void mma_tf32(float c[4],
                                         uint32_t a0, uint32_t a1, uint32_t a2, uint32_t a3,
                                         uint32_t b0, uint32_t b1) {
    asm("mma.sync.aligned.m16n8k8.row.col.f32.tf32.tf32.f32 "
        "{%0,%1,%2,%3},{%4,%5,%6,%7},{%8,%9},{%0,%1,%2,%3};"
        : "+f"(c[0]), "+f"(c[1]), "+f"(c[2]), "+f"(c[3])
        : "r"(a0), "r"(a1), "r"(a2), "r"(a3), "r"(b0), "r"(b1));
}

// Pre-kernel: build fragment-major tf32 W in global. 12 blocks, one per n-tile j.
__global__ void wfrag_kernel(const float* __restrict__ Wq,
                             const float* __restrict__ Wk,
                             const float* __restrict__ Wv) {
    int j = blockIdx.x;                    // 0..11
    const float* Wm = (j < 4) ? Wq : (j < 8) ? Wk : Wv;
    int nbase = (j & 3) * 8;
    for (int i = threadIdx.x; i < 512; i += blockDim.x) {   // i = ks*32 + lane
        int ks = i >> 5, lane = i & 31;
        int gid = lane >> 2, tig = lane & 3;
        int n = nbase + gid;
        g_Wfrag[(j * 512 + i) * 2 + 0] = f2tf(Wm[(8 * ks + tig)     * HD + n]);
        g_Wfrag[(j * 512 + i) * 2 + 1] = f2tf(Wm[(8 * ks + tig + 4) * HD + n]);
    }
}

__global__ __launch_bounds__(NTHREADS, 4)
void head_attn_kernel(const float* __restrict__ x,
                      const float* __restrict__ Wq,
                      const float* __restrict__ Wk,
                      const float* __restrict__ Wv,
                      float* __restrict__ out) {
    extern __shared__ float smem[];
    uint32_t* xh  = reinterpret_cast<uint32_t*>(smem + OFF_XH);  // x quarter, k-permuted
    uint32_t* Wh  = reinterpret_cast<uint32_t*>(smem + OFF_WH);  // Wfrag quarter
    uint32_t* qu  = reinterpret_cast<uint32_t*>(smem + OFF_Q);
    uint32_t* ku  = reinterpret_cast<uint32_t*>(smem + OFF_K);
    uint32_t* vT  = reinterpret_cast<uint32_t*>(smem + OFF_VT);
    uint32_t* scb = reinterpret_cast<uint32_t*>(smem + OFF_XH);  // overlay staging

    const int tid  = threadIdx.x;
    const int warp = tid >> 5;
    const int lane = tid & 31;
    const int gid  = lane >> 2;
    const int tig  = lane & 3;
    const int b    = blockIdx.x;
    const float* xb = x + (size_t)b * (TT * CC);

    const int sl0 = PSLOT8(2 * tig);       // slot of local col 2*tig
    const int sl1 = PSLOT8(2 * tig + 1);

    // ---------------- Phase 1: QKV, 4-stage K-quarter staging ----------------
    {
        const int m0    = (warp & 3) * 16;
        const int jbase = (warp >> 2) * 6;   // n-tiles jbase..jbase+5

        float acc[6][4];
        #pragma unroll
        for (int j = 0; j < 6; j++)
            #pragma unroll
            for (int t = 0; t < 4; t++) acc[j][t] = 0.0f;

        #pragma unroll
        for (int s = 0; s < 4; s++) {
            if (s) __syncthreads();

            // stage x[:, 32s..32s+32) k-permuted tf32 [64][40]
            {
                int r  = tid >> 2;
                int c0 = (tid & 3) * 8;
                const float* p = xb + r * CC + 32 * s + c0;
                float4 va = *reinterpret_cast<const float4*>(p);
                float4 vb = *reinterpret_cast<const float4*>(p + 4);
                uint4 o0 = make_uint4(f2tf(va.x), f2tf(vb.x), f2tf(va.y), f2tf(vb.y));
                uint4 o1 = make_uint4(f2tf(va.z), f2tf(vb.z), f2tf(va.w), f2tf(vb.w));
                *reinterpret_cast<uint4*>(xh + r * XHS + c0)     = o0;
                *reinterpret_cast<uint4*>(xh + r * XHS + c0 + 4) = o1;
            }
            // stage Wfrag quarter: ks in {4s..4s+3}, all 12 j
            #pragma unroll
            for (int ii = 0; ii < 3; ii++) {
                int i  = tid + ii * NTHREADS;       // 0..767 uint4
                int j  = i >> 6;
                int rm = i & 63;
                int kq = rm >> 4;
                int u  = rm & 15;
                uint4 v = reinterpret_cast<const uint4*>(g_Wfrag)
                              [j * 256 + (4 * s + kq) * 16 + u];
                *reinterpret_cast<uint4*>(Wh + j * 256 + kq * 64 + 4 * u) = v;
            }
            __syncthreads();

            #pragma unroll
            for (int kk = 0; kk < 32; kk += 8) {
                int ksl = kk >> 3;
                uint2 aA = *reinterpret_cast<const uint2*>(
                    xh + (m0 + gid)     * XHS + kk + 2 * tig);   // {a0, a2}
                uint2 aB = *reinterpret_cast<const uint2*>(
                    xh + (m0 + gid + 8) * XHS + kk + 2 * tig);   // {a1, a3}
                #pragma unroll
                for (int j = 0; j < 6; j++) {
                    uint2 bb = *reinterpret_cast<const uint2*>(
                        Wh + (jbase + j) * 256 + ksl * 64 + lane * 2);
                    mma_tf32(acc[j], aA.x, aB.x, aA.y, aB.y, bb.x, bb.y);
                }
            }
        }

        // scatter: n<32 -> q (d-permuted); 32..63 -> k (d-permuted); >=64 -> vT (seq-permuted)
        const int rsl = PSLOT8(gid);   // permuted seq slot base for vT
        #pragma unroll
        for (int j = 0; j < 6; j++) {
            int n0 = (jbase + j) * 8;
            #pragma unroll
            for (int half = 0; half < 2; half++) {
                int row = m0 + gid + 8 * half;
                uint32_t u0 = f2tf(acc[j][2 * half]);
                uint32_t u1 = f2tf(acc[j][2 * half + 1]);
                if (n0 < 32) {
                    qu[row * QSS + n0 + sl0] = u0;
                    qu[row * QSS + n0 + sl1] = u1;
                } else if (n0 < 64) {
                    ku[row * KSS + (n0 - 32) + sl0] = u0;
                    ku[row * KSS + (n0 - 32) + sl1] = u1;
                } else {
                    int rp = (row & ~7) | rsl;
                    vT[(n0 - 64 + 2 * tig)     * VTS + rp] = u0;
                    vT[(n0 - 64 + 2 * tig + 1) * VTS + rp] = u1;
                }
            }
        }
    }
    __syncthreads();

    // ---------------- Phase 2: scores (q @ k^T), causal tile skip ----------------
    {
        const int i  = warp & 3;
        const int m0 = 16 * i;
        const int jb = warp >> 2;
        int jn[4], cnt = 0;
        #pragma unroll
        for (int t = 0; t < 4; t++) {
            int j = jb + 2 * t;
            if (j <= 2 * i + 1) jn[cnt++] = j;
        }

        float acc[4][4];
        #pragma unroll
        for (int t = 0; t < 4; t++)
            #pragma unroll
            for (int e = 0; e < 4; e++) acc[t][e] = 0.0f;

        for (int k0 = 0; k0 < HD; k0 += 8) {
            uint2 aA = *reinterpret_cast<const uint2*>(
                qu + (m0 + gid)     * QSS + k0 + 2 * tig);
            uint2 aB = *reinterpret_cast<const uint2*>(
                qu + (m0 + gid + 8) * QSS + k0 + 2 * tig);
            for (int t = 0; t < cnt; t++) {
                int n0 = 8 * jn[t];
                uint2 bb = *reinterpret_cast<const uint2*>(
                    ku + (n0 + gid) * KSS + k0 + 2 * tig);
                mma_tf32(acc[t], aA.x, aB.x, aA.y, aB.y, bb.x, bb.y);
            }
        }

        const float scale = 0.17677669529663687f;   // 1/sqrt(32)
        for (int t = 0; t < cnt; t++) {
            int n0 = 8 * jn[t];
            #pragma unroll
            for (int half = 0; half < 2; half++) {
                int row = m0 + gid + 8 * half;
                scb[row * SCS + n0 + sl0] = __float_as_uint(acc[t][2 * half]     * scale);
                scb[row * SCS + n0 + sl1] = __float_as_uint(acc[t][2 * half + 1] * scale);
            }
        }
    }
    __syncthreads();

    // ---------------- Phase 3: causal softmax over permuted columns ----------------
    {
        const int colL = ((lane >> 1) & 3) | ((lane & 1) << 2);   // inv-perm
        const int col1 = (lane & ~7) | colL;
        for (int r = warp; r < TT; r += 8) {
            uint32_t* row = scb + r * SCS;
            bool v0 = (col1 <= r);
            bool v1 = (col1 + 32 <= r);
            float s0 = v0 ? __uint_as_float(row[lane])      : -1e30f;
            float s1 = v1 ? __uint_as_float(row[lane + 32]) : -1e30f;
            float m = fmaxf(s0, s1);
            #pragma unroll
            for (int off = 16; off > 0; off >>= 1)
                m = fmaxf(m, __shfl_xor_sync(0xffffffffu, m, off));
            float e0 = v0 ? __expf(s0 - m) : 0.0f;
            float e1 = v1 ? __expf(s1 - m) : 0.0f;
            float sum = e0 + e1;
            #pragma unroll
            for (int off = 16; off > 0; off >>= 1)
                sum += __shfl_xor_sync(0xffffffffu, sum, off);
            float inv = 1.0f / sum;
            row[lane]      = f2tf(e0 * inv);
            row[lane + 32] = f2tf(e1 * inv);
        }
    }
    __syncthreads();

    // ---------------- Phase 4: out = P @ V, causal K truncation ----------------
    {
        const int i  = warp & 3;
        const int m0 = 16 * i;
        const int jb = warp >> 2;

        float acc[2][4];
        #pragma unroll
        for (int t = 0; t < 2; t++)
            #pragma unroll
            for (int e = 0; e < 4; e++) acc[t][e] = 0.0f;

        const int kend = 16 * i + 8;
        for (int k0 = 0; k0 <= kend; k0 += 8) {
            uint2 aA = *reinterpret_cast<const uint2*>(
                scb + (m0 + gid)     * SCS + k0 + 2 * tig);
            uint2 aB = *reinterpret_cast<const uint2*>(
                scb + (m0 + gid + 8) * SCS + k0 + 2 * tig);
            #pragma unroll
            for (int t = 0; t < 2; t++) {
                int n0 = 8 * (jb + 2 * t);
                uint2 bb = *reinterpret_cast<const uint2*>(
                    vT + (n0 + gid) * VTS + k0 + 2 * tig);
                mma_tf32(acc[t], aA.x, aB.x, aA.y, aB.y, bb.x, bb.y);
            }
        }

        float* ob = out + (size_t)b * (TT * HD);
        #pragma unroll
        for (int t = 0; t < 2; t++) {
            int c = 8 * (jb + 2 * t) + 2 * tig;
            #pragma unroll
            for (int half = 0; half < 2; half++) {
                int row = m0 + gid + 8 * half;
                *reinterpret_cast<float2*>(ob + row * HD + c) =
                    make_float2(acc[t][2 * half], acc[t][2 * half + 1]);
            }
        }
    }
}

extern "C" void kernel_launch(void* const* d_in, const int* in_sizes, int n_in,
                              void* d_out, int out_size) {
    const float* x  = (const float*)d_in[0];
    const float* Wq = (const float*)d_in[1];
    const float* Wk = (const float*)d_in[2];
    const float* Wv = (const float*)d_in[3];
    float* out = (float*)d_out;

    const int B = in_sizes[0] / (TT * CC);   // 4096
    const size_t smem_bytes = SMEM_WORDS * sizeof(float);

    static_assert(4 * (SMEM_WORDS * sizeof(float) + 1024) <= 228 * 1024,
                  "4 CTAs/SM incl. per-CTA reserve");
    cudaFuncSetAttribute(head_attn_kernel,
                         cudaFuncAttributeMaxDynamicSharedMemorySize,
                         (int)smem_bytes);

    wfrag_kernel<<<12, 256>>>(Wq, Wk, Wv);
    head_attn_kernel<<<B, NTHREADS, smem_bytes>>>(x, Wq, Wk, Wv, out);
}

// round 13
// speedup vs baseline: 1.0290x; 1.0290x over previous
#include <cuda_runtime.h>
#include <cstdint>

#define TT 64
#define CC 128
#define HD 32
#define NTHREADS 256

// Bank rules (lane = 4*gid + tig):
//  A loads  arr[(m0+gid)*S + kk+tig]   -> S ≡ 4 (mod 32)
//  B loads  arr[(kk+tig)*S + n0+gid]   -> S ≡ 8 (mod 32)
//  B loads  arr[(n0+gid)*S + kk+tig]   -> S ≡ 4 (mod 32)
#define XHS 36     // x quarter fp32-raw [64][36]  (A)  extent 32 ✓
#define WHS 104    // W quarter tf32 [32][104]     (B)  extent 96 ✓
#define SCS 68     // scores/probs [64][68] (A, overlays staging region)
#define QSS 36     // q tf32 [64][36]  (A)             extent 32 ✓
#define KSS 36     // k tf32 [64][36]  (B via n-major) extent 32 ✓
#define VTS 68     // vT tf32 [32][68] (B via n-major) extent 64 ✓

#define OFF_XH 0
#define OFF_WH (TT * XHS)                  // 2304 words (byte 9216, 16B-aligned)
#define STAGE_WORDS (OFF_WH + 32 * WHS)    // 5632  (sc overlay 64*68=4352 fits)
#define OFF_Q  STAGE_WORDS                 // 5632
#define OFF_K  (OFF_Q + TT * QSS)          // 7936
#define OFF_VT (OFF_K + TT * KSS)          // 10240
#define SMEM_WORDS (OFF_VT + HD * VTS)     // 12416 words = 49664 B

// W pre-converted to tf32, laid out [128][104] (stride matches smem Wh)
__device__ uint32_t g_Wtf[CC * WHS];

__device__ __forceinline__ uint32_t f2tf(float f) {
    uint32_t u;
    asm("cvt.rna.tf32.f32 %0, %1;" : "=r"(u) : "f"(f));
    return u;
}
__device__ __forceinline__ uint32_t smem_u32(const void* p) {
    uint32_t a;
    asm("{ .reg .u64 t; cvta.to.shared.u64 t, %1; cvt.u32.u64 %0, t; }"
        : "=r"(a) : "l"(p));
    return a;
}
__device__ __forceinline__ void cp_async16(uint32_t dst, const void* src) {
    asm volatile("cp.async.ca.shared.global [%0], [%1], 16;"
                 :: "r"(dst), "l"(src));
}
__device__ __forceinline__ void cp_async_commit_wait() {
    asm volatile("cp.async.commit_group;");
    asm volatile("cp.async.wait_group 0;");
}
__device__ __forceinline__ void mma_tf32(float c[4],
                                         uint32_t a0, uint32_t a1, uint32_t a2, uint32_t a3,
                                         uint32_t b0, uint32_t b1) {
    asm("mma.sync.aligned.m16n8k8.row.col.f32.tf32.tf32.f32 "
        "{%0,%1,%2,%3},{%4,%5,%6,%7},{%8,%9},{%0,%1,%2,%3};"
        : "+f"(c[0]), "+f"(c[1]), "+f"(c[2]), "+f"(c[3])
        : "r"(a0), "r"(a1), "r"(a2), "r"(a3), "r"(b0), "r"(b1));
}

// Pre-kernel: tf32-convert W into [128][104] global (pad cols 96-103 zero).
__global__ void wtf_kernel(const float* __restrict__ Wq,
                           const float* __restrict__ Wk,
                           const float* __restrict__ Wv) {
    int i = blockIdx.x * 256 + threadIdx.x;    // grid 52*256 = 13312 = 128*104
    int d = i / WHS, c = i % WHS;
    uint32_t u = 0;
    if (c < 32)       u = f2tf(Wq[d * HD + c]);
    else if (c < 64)  u = f2tf(Wk[d * HD + (c - 32)]);
    else if (c < 96)  u = f2tf(Wv[d * HD + (c - 64)]);
    g_Wtf[i] = u;
}

__global__ __launch_bounds__(NTHREADS, 4)
void head_attn_kernel(const float* __restrict__ x,
                      float* __restrict__ out) {
    extern __shared__ float smem[];
    uint32_t* xh  = reinterpret_cast<uint32_t*>(smem + OFF_XH);  // x raw fp32 bits
    uint32_t* Wh  = reinterpret_cast<uint32_t*>(smem + OFF_WH);  // W quarter tf32
    uint32_t* qu  = reinterpret_cast<uint32_t*>(smem + OFF_Q);   // q tf32 [seq][d]
    uint32_t* ku  = reinterpret_cast<uint32_t*>(smem + OFF_K);   // k tf32 [seq][d]
    uint32_t* vT  = reinterpret_cast<uint32_t*>(smem + OFF_VT);  // vT tf32 [d][seq]
    uint32_t* scb = xh;   // scores/probs overlay staging region, stride SCS

    const int tid  = threadIdx.x;
    const int warp = tid >> 5;
    const int lane = tid & 31;
    const int gid  = lane >> 2;   // 0..7
    const int tig  = lane & 3;    // 0..3
    const int b    = blockIdx.x;
    const float* xb = x + (size_t)b * (TT * CC);

    const uint32_t xh_b = smem_u32(xh);
    const uint32_t Wh_b = smem_u32(Wh);

    // ---------------- Phase 1: QKV via tf32 MMA, 4-stage K-quarter cp.async staging ----------------
    // M=64, N=96, K=128 in 4 stages of K=32. warp: m-tile=warp&3, n-tiles=6*(warp>>2)+0..5
    {
        const int m0    = (warp & 3) * 16;
        const int nbase = (warp >> 2) * 48;

        float acc[6][4];
        #pragma unroll
        for (int j = 0; j < 6; j++)
            #pragma unroll
            for (int t = 0; t < 4; t++) acc[j][t] = 0.0f;

        #pragma unroll
        for (int s = 0; s < 4; s++) {
            if (s) __syncthreads();   // prior-stage consumers done before overwrite

            // x[:, 32s..32s+32) raw fp32 -> xh [64][36], 16B cp.async
            #pragma unroll
            for (int ii = 0; ii < 2; ii++) {
                int i = tid + ii * NTHREADS;
                int idx = i * 4;
                int r = idx >> 5, c = idx & 31;
                cp_async16(xh_b + (r * XHS + c) * 4, xb + r * CC + 32 * s + c);
            }
            // W quarter: contiguous block copy g_Wtf[32s..32s+32][0..104) -> Wh
            #pragma unroll
            for (int ii = 0; ii < 3; ii++) {
                int u = tid + ii * NTHREADS;          // 0..767
                cp_async16(Wh_b + u * 16, g_Wtf + s * 32 * WHS + u * 4);
            }
            if (tid < 64) {                           // tail 768..831
                int u = tid + 768;
                cp_async16(Wh_b + u * 16, g_Wtf + s * 32 * WHS + u * 4);
            }
            cp_async_commit_wait();
            __syncthreads();

            #pragma unroll
            for (int kk = 0; kk < 32; kk += 8) {
                uint32_t a0 = xh[(m0 + gid)     * XHS + kk + tig];
                uint32_t a1 = xh[(m0 + gid + 8) * XHS + kk + tig];
                uint32_t a2 = xh[(m0 + gid)     * XHS + kk + tig + 4];
                uint32_t a3 = xh[(m0 + gid + 8) * XHS + kk + tig + 4];
                #pragma unroll
                for (int j = 0; j < 6; j++) {
                    int n0 = nbase + 8 * j;
                    uint32_t b0 = Wh[(kk + tig)     * WHS + n0 + gid];
                    uint32_t b1 = Wh[(kk + tig + 4) * WHS + n0 + gid];
                    mma_tf32(acc[j], a0, a1, a2, a3, b0, b1);
                }
            }
        }

        // scatter as tf32: n<32 -> q [seq][d]; 32..63 -> k [seq][d]; >=64 -> vT [d][seq]
        #pragma unroll
        for (int j = 0; j < 6; j++) {
            int n0 = nbase + 8 * j;
            int c  = n0 + 2 * tig;
            #pragma unroll
            for (int half = 0; half < 2; half++) {
                int row = m0 + gid + 8 * half;
                uint32_t u0 = f2tf(acc[j][2 * half]);
                uint32_t u1 = f2tf(acc[j][2 * half + 1]);
                if (n0 < 32) {
                    qu[row * QSS + c]     = u0;
                    qu[row * QSS + c + 1] = u1;
                } else if (n0 < 64) {
                    ku[row * KSS + (c - 32)] = u0;
                    ku[row * KSS + (c - 31)] = u1;
                } else {
                    vT[(c - 64) * VTS + row] = u0;
                    vT[(c - 63) * VTS + row] = u1;
                }
            }
        }
    }
    __syncthreads();

    // ---------------- Phase 2: scores via tf32 MMA ----------------
    // M=64, N=64, K=32. warp: m-tile i=warp&3, n-tiles j=(warp>>2)+2t, j<=2i+1
    {
        const int i  = warp & 3;
        const int m0 = 16 * i;
        const int jb = warp >> 2;
        int jn[4], cnt = 0;
        #pragma unroll
        for (int t = 0; t < 4; t++) {
            int j = jb + 2 * t;
            if (j <= 2 * i + 1) jn[cnt++] = j;
        }

        float acc[4][4];
        #pragma unroll
        for (int t = 0; t < 4; t++)
            #pragma unroll
            for (int e = 0; e < 4; e++) acc[t][e] = 0.0f;

        for (int k0 = 0; k0 < HD; k0 += 8) {
            uint32_t a0 = qu[(m0 + gid)     * QSS + k0 + tig];
            uint32_t a1 = qu[(m0 + gid + 8) * QSS + k0 + tig];
            uint32_t a2 = qu[(m0 + gid)     * QSS + k0 + tig + 4];
            uint32_t a3 = qu[(m0 + gid + 8) * QSS + k0 + tig + 4];
            for (int t = 0; t < cnt; t++) {
                int n0 = 8 * jn[t];
                uint32_t b0 = ku[(n0 + gid) * KSS + k0 + tig];
                uint32_t b1 = ku[(n0 + gid) * KSS + k0 + tig + 4];
                mma_tf32(acc[t], a0, a1, a2, a3, b0, b1);
            }
        }

        const float scale = 0.17677669529663687f;   // 1/sqrt(32)
        for (int t = 0; t < cnt; t++) {
            int n0 = 8 * jn[t];
            int c  = n0 + 2 * tig;
            #pragma unroll
            for (int half = 0; half < 2; half++) {
                int row = m0 + gid + 8 * half;
                scb[row * SCS + c]     = __float_as_uint(acc[t][2 * half]     * scale);
                scb[row * SCS + c + 1] = __float_as_uint(acc[t][2 * half + 1] * scale);
            }
        }
    }
    __syncthreads();

    // ---------------- Phase 3: causal softmax; probs written as tf32 bits ----------------
    {
        for (int r = warp; r < TT; r += 8) {
            uint32_t* row = scb + r * SCS;
            bool v0 = (lane <= r);
            bool v1 = (lane + 32 <= r);
            float s0 = v0 ? __uint_as_float(row[lane])      : -1e30f;
            float s1 = v1 ? __uint_as_float(row[lane + 32]) : -1e30f;
            float m = fmaxf(s0, s1);
            #pragma unroll
            for (int off = 16; off > 0; off >>= 1)
                m = fmaxf(m, __shfl_xor_sync(0xffffffffu, m, off));
            float e0 = v0 ? __expf(s0 - m) : 0.0f;
            float e1 = v1 ? __expf(s1 - m) : 0.0f;
            float sum = e0 + e1;
            #pragma unroll
            for (int off = 16; off > 0; off >>= 1)
                sum += __shfl_xor_sync(0xffffffffu, sum, off);
            float inv = 1.0f / sum;
            row[lane]      = f2tf(e0 * inv);   // tf32(0) = 0 where masked
            row[lane + 32] = f2tf(e1 * inv);
        }
    }
    __syncthreads();

    // ---------------- Phase 4: out = P @ V via tf32 MMA ----------------
    // M=64, N=32, K=64 causal-truncated. warp: m-tile i=warp&3, n-tiles jb, jb+2
    {
        const int i  = warp & 3;
        const int m0 = 16 * i;
        const int jb = warp >> 2;

        float acc[2][4];
        #pragma unroll
        for (int t = 0; t < 2; t++)
            #pragma unroll
            for (int e = 0; e < 4; e++) acc[t][e] = 0.0f;

        const int kend = 16 * i + 8;   // probs beyond are exact zeros
        for (int k0 = 0; k0 <= kend; k0 += 8) {
            uint32_t a0 = scb[(m0 + gid)     * SCS + k0 + tig];
            uint32_t a1 = scb[(m0 + gid + 8) * SCS + k0 + tig];
            uint32_t a2 = scb[(m0 + gid)     * SCS + k0 + tig + 4];
            uint32_t a3 = scb[(m0 + gid + 8) * SCS + k0 + tig + 4];
            #pragma unroll
            for (int t = 0; t < 2; t++) {
                int n0 = 8 * (jb + 2 * t);
                uint32_t b0 = vT[(n0 + gid) * VTS + k0 + tig];
                uint32_t b1 = vT[(n0 + gid) * VTS + k0 + tig + 4];
                mma_tf32(acc[t], a0, a1, a2, a3, b0, b1);
            }
        }

        float* ob = out + (size_t)b * (TT * HD);
        #pragma unroll
        for (int t = 0; t < 2; t++) {
            int n0 = 8 * (jb + 2 * t);
            int c  = n0 + 2 * tig;
            #pragma unroll
            for (int half = 0; half < 2; half++) {
                int row = m0 + gid + 8 * half;
                *reinterpret_cast<float2*>(ob + row * HD + c) =
                    make_float2(acc[t][2 * half], acc[t][2 * half + 1]);
            }
        }
    }
}

extern "C" void kernel_launch(void* const* d_in, const int* in_sizes, int n_in,
                              void* d_out, int out_size) {
    const float* x  = (const float*)d_in[0];
    const float* Wq = (const float*)d_in[1];
    const float* Wk = (const float*)d_in[2];
    const float* Wv = (const float*)d_in[3];
    float* out = (float*)d_out;

    const int B = in_sizes[0] / (TT * CC);   // 4096
    const size_t smem_bytes = SMEM_WORDS * sizeof(float);

    static_assert(4 * (SMEM_WORDS * sizeof(float) + 1024) <= 228 * 1024,
                  "4 CTAs/SM incl. per-CTA reserve");
    cudaFuncSetAttribute(head_attn_kernel,
                         cudaFuncAttributeMaxDynamicSharedMemorySize,
                         (int)smem_bytes);

    wtf_kernel<<<52, 256>>>(Wq, Wk, Wv);
    head_attn_kernel<<<B, NTHREADS, smem_bytes>>>(x, out);
}